// round 11
// baseline (speedup 1.0000x reference)
#include <cuda_runtime.h>
#include <math.h>
#include <stdint.h>

#define HDIM 1024
#define MD   2048
#define LMEM 16384
#define NH   8
#define DH   128
#define TPB  256
#define TR   8
#define NT   (LMEM/TR)     // 2048 tiles
#define GB   152           // GB300 has 152 SMs
#define NGRP 8             // k_comb split: 152 = 8*19
#define BBG  (GB/NGRP)     // 19
#define QSCALE 0.08838834764831845f   // 1/sqrt(128)

// __device__ scratch (no allocations allowed)
__device__ float g_q[HDIM];
__device__ float g_w8[MD*NH];
__device__ float g_pm[GB*NH];
__device__ float g_pz[GB*NH];
__device__ float g_pp[GB*NH*MD];
__device__ float g_pool8[NGRP*NH*MD];
__device__ float g_pooled[NH*MD];
__device__ float g_feat[HDIM];

__device__ __forceinline__ float warp_sum(float v){
#pragma unroll
    for (int o = 16; o; o >>= 1) v += __shfl_xor_sync(0xffffffffu, v, o);
    return v;
}
__device__ __forceinline__ float warp_max(float v){
#pragma unroll
    for (int o = 16; o; o >>= 1) v = fmaxf(v, __shfl_xor_sync(0xffffffffu, v, o));
    return v;
}

__device__ __forceinline__ void cp16(float* dst, const float* src){
    uint32_t s = (uint32_t)__cvta_generic_to_shared(dst);
    asm volatile("cp.async.cg.shared.global [%0], [%1], 16;" :: "r"(s), "l"(src));
}

// ---------------- k1: q = x @ Wq^T + bq  (warp per output) ----------------
__global__ __launch_bounds__(TPB) void k_q(const float* __restrict__ x,
                                           const float* __restrict__ Wq,
                                           const float* __restrict__ bq){
    int lane = threadIdx.x & 31;
    int h = blockIdx.x * 8 + (threadIdx.x >> 5);
    const float4* xr = (const float4*)x;
    const float4* wr = (const float4*)(Wq + (size_t)h * HDIM);
    float acc = 0.f;
#pragma unroll
    for (int i = 0; i < 8; i++){
        float4 a = wr[lane + 32*i];
        float4 b = xr[lane + 32*i];
        acc += a.x*b.x + a.y*b.y + a.z*b.z + a.w*b.w;
    }
    acc = warp_sum(acc);
    if (lane == 0) g_q[h] = acc + bq[h];
}

// ---------- k2: w8[m][n] = QSCALE * sum_i q[i*8+n] * Wk[i*8+n][m] ----------
#define WTPB 128
__global__ __launch_bounds__(WTPB) void k_w8(const float* __restrict__ Wk){
    int n = blockIdx.x & 7;
    int m = (blockIdx.x >> 3) * WTPB + threadIdx.x;
    __shared__ float qs[DH];
    qs[threadIdx.x] = g_q[threadIdx.x * NH + n] * QSCALE;   // 128 threads == DH
    __syncthreads();
    float acc = 0.f;
#pragma unroll 8
    for (int i = 0; i < DH; i++)
        acc += qs[i] * Wk[(size_t)(i*NH + n)*MD + m];
    g_w8[m*NH + n] = acc;
}

// ---------------- k3: fused scores + online softmax + pooling ----------------
__global__ __launch_bounds__(TPB, 1) void k_main(const float* __restrict__ mem){
    extern __shared__ float sm[];
    float* rowbuf = sm;                       // 2*TR*MD
    float* part   = sm + 2*TR*MD;             // TR*NH*TPB
    float* srow   = part + TR*NH*TPB;         // TR*NH
    float* esm    = srow + TR*NH;             // TR*NH
    float* scs    = esm + TR*NH;              // NH
    int*   sflag  = (int*)(scs + NH);         // 1
    const int t = threadIdx.x, b = blockIdx.x;
    const int lane = t & 31, wid = t >> 5;

    const int baseCnt = NT / GB, rem = NT % GB;
    const int cnt   = baseCnt + (b < rem ? 1 : 0);
    const int start = b * baseCnt + (b < rem ? b : rem);

    // per-thread slice of w8: [k][n]
    float w[8][8];
#pragma unroll
    for (int k = 0; k < 8; k++){
        int c = (k < 4) ? (t*4 + k) : (1024 + t*4 + (k - 4));
        const float4* wp = (const float4*)(g_w8 + c*8);
        float4 a = wp[0], d4 = wp[1];
        w[k][0]=a.x;  w[k][1]=a.y;  w[k][2]=a.z;  w[k][3]=a.w;
        w[k][4]=d4.x; w[k][5]=d4.y; w[k][6]=d4.z; w[k][7]=d4.w;
    }
    float p[8][8];   // [n][k] pooled accumulators
#pragma unroll
    for (int n = 0; n < 8; n++)
#pragma unroll
        for (int k = 0; k < 8; k++) p[n][k] = 0.f;
    float mcur = -INFINITY, Zc = 0.f;   // live in warp0 lanes<8

    auto issue = [&](int tileIdx, int dbuf){
        const float* src = mem + (size_t)tileIdx * (TR*MD);
        float* dst = rowbuf + dbuf * (TR*MD);
#pragma unroll
        for (int j = 0; j < 16; j++){
            int idx = t + j*TPB;
            cp16(dst + idx*4, src + idx*4);
        }
    };
    if (cnt > 0) issue(start, 0);
    asm volatile("cp.async.commit_group;");
    if (cnt > 1) issue(start + 1, 1);
    asm volatile("cp.async.commit_group;");

    for (int it = 0; it < cnt; it++){
        asm volatile("cp.async.wait_group 1;");
        __syncthreads();
        const float* buf = rowbuf + (it & 1) * (TR*MD);

        // Phase A: per-thread partial scores for all TR rows x 8 heads
#pragma unroll
        for (int r = 0; r < TR; r++){
            const float4* rp = (const float4*)(buf + r*MD + t*4);
            float4 r0 = rp[0], r1 = rp[256];
            float rv[8] = {r0.x,r0.y,r0.z,r0.w, r1.x,r1.y,r1.z,r1.w};
            float acc[8];
#pragma unroll
            for (int n = 0; n < 8; n++) acc[n] = rv[0]*w[0][n];
#pragma unroll
            for (int k = 1; k < 8; k++)
#pragma unroll
                for (int n = 0; n < 8; n++) acc[n] += rv[k]*w[k][n];
#pragma unroll
            for (int n = 0; n < 8; n++) part[(r*8 + n)*TPB + t] = acc[n];
        }
        __syncthreads();

        // Phase B: warp r reduces its row's 8 head-partials over 256 threads
        {
            int r = wid;
#pragma unroll
            for (int n = 0; n < 8; n++){
                const float4* pp = (const float4*)(part + (r*8 + n)*TPB);
                float4 a = pp[lane*2], c4 = pp[lane*2 + 1];
                float v = (a.x + a.y) + (a.z + a.w) + (c4.x + c4.y) + (c4.z + c4.w);
                v = warp_sum(v);
                if (lane == 0) srow[r*8 + n] = v;
            }
        }
        __syncthreads();

        // Phase C: online-softmax bookkeeping (warp 0; lanes<8 do the work)
        if (wid == 0){
            float sc = 1.f;
            if (lane < 8){
                int n = lane;
                float tm = srow[n];
#pragma unroll
                for (int r = 1; r < TR; r++) tm = fmaxf(tm, srow[r*8 + n]);
                float mnew = fmaxf(mcur, tm);
                sc = __expf(mcur - mnew);   // 0 on first tile
                float zl = 0.f;
#pragma unroll
                for (int r = 0; r < TR; r++){
                    float e = __expf(srow[r*8 + n] - mnew);
                    esm[r*8 + n] = e;
                    zl += e;
                }
                Zc = Zc*sc + zl;
                mcur = mnew;
                scs[n] = sc;
            }
            unsigned bal = __ballot_sync(0xffffffffu, (lane < 8) ? (sc == 1.f) : true);
            if (lane == 0) *sflag = (bal == 0xffffffffu);
        }
        __syncthreads();

        // Phase D: (conditional) rescale + weighted accumulation of rows
        {
            if (!*sflag){
                float s8[8];
                const float4* sp = (const float4*)scs;
                float4 a = sp[0], d4 = sp[1];
                s8[0]=a.x; s8[1]=a.y; s8[2]=a.z; s8[3]=a.w;
                s8[4]=d4.x; s8[5]=d4.y; s8[6]=d4.z; s8[7]=d4.w;
#pragma unroll
                for (int n = 0; n < 8; n++)
#pragma unroll
                    for (int k = 0; k < 8; k++) p[n][k] *= s8[n];
            }
#pragma unroll
            for (int r = 0; r < TR; r++){
                const float4* rp = (const float4*)(buf + r*MD + t*4);
                float4 r0 = rp[0], r1 = rp[256];
                float rv[8] = {r0.x,r0.y,r0.z,r0.w, r1.x,r1.y,r1.z,r1.w};
                const float4* ep = (const float4*)(esm + r*8);
                float4 e0 = ep[0], e1 = ep[1];
                float ev[8] = {e0.x,e0.y,e0.z,e0.w, e1.x,e1.y,e1.z,e1.w};
#pragma unroll
                for (int n = 0; n < 8; n++)
#pragma unroll
                    for (int k = 0; k < 8; k++) p[n][k] += ev[n]*rv[k];
            }
        }
        __syncthreads();
        if (it + 2 < cnt) issue(start + it + 2, it & 1);
        asm volatile("cp.async.commit_group;");
    }

    // write per-block partial (m, Z, pooled)
    if (t < 8){ g_pm[b*8 + t] = mcur; g_pz[b*8 + t] = Zc; }
#pragma unroll
    for (int n = 0; n < 8; n++){
        float4 s0 = make_float4(p[n][0], p[n][1], p[n][2], p[n][3]);
        float4 s1 = make_float4(p[n][4], p[n][5], p[n][6], p[n][7]);
        float* dst = g_pp + (size_t)(b*8 + n)*MD;
        ((float4*)dst)[t]          = s0;        // cols t*4 ..
        ((float4*)(dst + 1024))[t] = s1;        // cols 1024+t*4 ..
    }
}

// ---- k_comb v3: float4 8-way split weighted reduction -> g_pool8 ----
#define CTPB 128
__global__ __launch_bounds__(CTPB) void k_comb(){
    // grid = NH * 4 * NGRP = 256 blocks
    int n      = blockIdx.x >> 5;                 // bits [5..7]: head
    int colblk = (blockIdx.x >> 3) & 3;           // bits [3..4]: col block
    int g      = blockIdx.x & 7;                  // bits [0..2]: bb group
    int c4     = colblk * CTPB + threadIdx.x;     // float4 col 0..511
    int lane = threadIdx.x & 31, wid = threadIdx.x >> 5;
    __shared__ float S[GB];
    __shared__ float invZsh;
    if (wid == 0){
        float m = -INFINITY;
#pragma unroll
        for (int j = 0; j < 5; j++){
            int bb = lane + 32*j;
            if (bb < GB) m = fmaxf(m, g_pm[bb*8 + n]);
        }
        m = warp_max(m);
        float z = 0.f;
#pragma unroll
        for (int j = 0; j < 5; j++){
            int bb = lane + 32*j;
            if (bb < GB){
                float s = __expf(g_pm[bb*8 + n] - m);
                S[bb] = s;
                z += g_pz[bb*8 + n] * s;
            }
        }
        z = warp_sum(z);
        if (lane == 0) invZsh = 1.f / z;
    }
    __syncthreads();
    const float4* base = (const float4*)g_pp + ((size_t)(g*BBG*8 + n) * 512 + c4);
    float ax = 0.f, ay = 0.f, az = 0.f, aw = 0.f;
#pragma unroll
    for (int bb = 0; bb < BBG; bb++){
        float s = S[g*BBG + bb];
        float4 v = base[(size_t)bb * (8*512)];
        ax += s*v.x; ay += s*v.y; az += s*v.z; aw += s*v.w;
    }
    float iz = invZsh;
    ((float4*)g_pool8)[(size_t)(g*8 + n)*512 + c4] =
        make_float4(ax*iz, ay*iz, az*iz, aw*iz);
}

// ---- k_pool: pooled[n][c] = sum_g pool8[g][n][c]  (32 blocks) ----
__global__ __launch_bounds__(CTPB) void k_pool(){
    int n      = blockIdx.x >> 2;                 // 8 heads
    int colblk = blockIdx.x & 3;
    int c4     = colblk * CTPB + threadIdx.x;     // 0..511
    const float4* base = (const float4*)g_pool8 + ((size_t)n * 512 + c4);
    float ax = 0.f, ay = 0.f, az = 0.f, aw = 0.f;
#pragma unroll
    for (int g = 0; g < NGRP; g++){
        float4 v = base[(size_t)g * (8*512)];
        ax += v.x; ay += v.y; az += v.z; aw += v.w;
    }
    ((float4*)g_pooled)[(size_t)n*512 + c4] = make_float4(ax, ay, az, aw);
}

// ---- k5: feat[h] = pooled[h%8].Wv[h,:] + bv[h]  (4 warps/output) ----
__global__ __launch_bounds__(TPB) void k_feat(const float* __restrict__ Wv,
                                              const float* __restrict__ bv){
    __shared__ float sh[2][4];
    int lane = threadIdx.x & 31, wid = threadIdx.x >> 5;
    int local = wid >> 2, q = wid & 3;
    int h = blockIdx.x * 2 + local;
    int n = h & 7;
    const float4* wr = (const float4*)(Wv + (size_t)h*MD) + q*128;
    const float4* pr = (const float4*)(g_pooled + (size_t)n*MD) + q*128;
    float acc = 0.f;
#pragma unroll
    for (int i = 0; i < 4; i++){
        int idx = lane + 32*i;
        float4 a = wr[idx];
        float4 v = pr[idx];
        acc += a.x*v.x + a.y*v.y + a.z*v.z + a.w*v.w;
    }
    acc = warp_sum(acc);
    if (lane == 0) sh[local][q] = acc;
    __syncthreads();
    if (threadIdx.x < 2){
        int hh = blockIdx.x * 2 + threadIdx.x;
        g_feat[hh] = sh[threadIdx.x][0] + sh[threadIdx.x][1]
                   + sh[threadIdx.x][2] + sh[threadIdx.x][3] + bv[hh];
    }
}

// ---- k6: out = relu([x,feat] @ Wo^T + bo)  (4 warps/output) ----
__global__ __launch_bounds__(TPB) void k_out(const float* __restrict__ x,
                                             const float* __restrict__ Wo,
                                             const float* __restrict__ bo,
                                             float* __restrict__ out){
    __shared__ float sh[2][4];
    int lane = threadIdx.x & 31, wid = threadIdx.x >> 5;
    int local = wid >> 2, q = wid & 3;
    int o = blockIdx.x * 2 + local;
    const float4* wr = (const float4*)(Wo + (size_t)o*(2*HDIM)) + q*128;
    const float4* vr = ((q < 2) ? (const float4*)x : (const float4*)g_feat) + (q & 1)*128;
    float acc = 0.f;
#pragma unroll
    for (int i = 0; i < 4; i++){
        int idx = lane + 32*i;
        float4 a = wr[idx];
        float4 v = vr[idx];
        acc += a.x*v.x + a.y*v.y + a.z*v.z + a.w*v.w;
    }
    acc = warp_sum(acc);
    if (lane == 0) sh[local][q] = acc;
    __syncthreads();
    if (threadIdx.x < 2){
        int oo = blockIdx.x * 2 + threadIdx.x;
        out[oo] = fmaxf(sh[threadIdx.x][0] + sh[threadIdx.x][1]
                      + sh[threadIdx.x][2] + sh[threadIdx.x][3] + bo[oo], 0.f);
    }
}

extern "C" void kernel_launch(void* const* d_in, const int* in_sizes, int n_in,
                              void* d_out, int out_size){
    (void)in_sizes; (void)n_in; (void)out_size;
    const float* x   = (const float*)d_in[0];
    const float* mem = (const float*)d_in[1];
    const float* Wq  = (const float*)d_in[2];
    const float* bq  = (const float*)d_in[3];
    const float* Wk  = (const float*)d_in[4];
    // d_in[5] = bk: constant per head -> cancels in softmax, unused
    const float* Wv  = (const float*)d_in[6];
    const float* bv  = (const float*)d_in[7];
    const float* Wo  = (const float*)d_in[8];
    const float* bo  = (const float*)d_in[9];
    float* out = (float*)d_out;

    const size_t smem = (size_t)(2*TR*MD + TR*NH*TPB + 2*TR*NH + NH + 1) * sizeof(float);
    cudaFuncSetAttribute(k_main, cudaFuncAttributeMaxDynamicSharedMemorySize, (int)smem);

    k_q   <<<HDIM/8,        TPB>>>(x, Wq, bq);
    k_w8  <<<(MD/WTPB)*NH,  WTPB>>>(Wk);
    k_main<<<GB,            TPB, smem>>>(mem);
    k_comb<<<NH*4*NGRP,     CTPB>>>();
    k_pool<<<NH*4,          CTPB>>>();
    k_feat<<<HDIM/2,        TPB>>>(Wv, bv);
    k_out <<<HDIM/2,        TPB>>>(x, Wo, bo, out);
}

// round 12
// speedup vs baseline: 1.2602x; 1.2602x over previous
#include <cuda_runtime.h>
#include <math.h>
#include <stdint.h>

#define HDIM 1024
#define MD   2048
#define LMEM 16384
#define NH   8
#define DH   128
#define TPB  256
#define MTPB 512           // k_main threads
#define TR   8
#define NT   (LMEM/TR)     // 2048 tiles
#define GB   152           // GB300 has 152 SMs
#define QSCALE 0.08838834764831845f   // 1/sqrt(128)

// __device__ scratch (no allocations allowed)
__device__ float g_q[HDIM];
__device__ float g_w8[MD*NH];
__device__ float g_pm[GB*NH];
__device__ float g_pz[GB*NH];
__device__ float g_pp[GB*NH*MD];
__device__ float g_pooled[NH*MD];
__device__ float g_feat[HDIM];

__device__ __forceinline__ float warp_sum(float v){
#pragma unroll
    for (int o = 16; o; o >>= 1) v += __shfl_xor_sync(0xffffffffu, v, o);
    return v;
}
__device__ __forceinline__ float warp_max(float v){
#pragma unroll
    for (int o = 16; o; o >>= 1) v = fmaxf(v, __shfl_xor_sync(0xffffffffu, v, o));
    return v;
}

__device__ __forceinline__ void cp16(float* dst, const float* src){
    uint32_t s = (uint32_t)__cvta_generic_to_shared(dst);
    asm volatile("cp.async.cg.shared.global [%0], [%1], 16;" :: "r"(s), "l"(src));
}

// ---------------- k1: q = x @ Wq^T + bq  (warp per output) ----------------
__global__ __launch_bounds__(TPB) void k_q(const float* __restrict__ x,
                                           const float* __restrict__ Wq,
                                           const float* __restrict__ bq){
    int lane = threadIdx.x & 31;
    int h = blockIdx.x * 8 + (threadIdx.x >> 5);
    const float4* xr = (const float4*)x;
    const float4* wr = (const float4*)(Wq + (size_t)h * HDIM);
    float acc = 0.f;
#pragma unroll
    for (int i = 0; i < 8; i++){
        float4 a = wr[lane + 32*i];
        float4 b = xr[lane + 32*i];
        acc += a.x*b.x + a.y*b.y + a.z*b.z + a.w*b.w;
    }
    acc = warp_sum(acc);
    if (lane == 0) g_q[h] = acc + bq[h];
}

// ---------- k2: w8[m][n] = QSCALE * sum_i q[i*8+n] * Wk[i*8+n][m] ----------
#define WTPB 128
__global__ __launch_bounds__(WTPB) void k_w8(const float* __restrict__ Wk){
    int n = blockIdx.x & 7;
    int m = (blockIdx.x >> 3) * WTPB + threadIdx.x;
    __shared__ float qs[DH];
    qs[threadIdx.x] = g_q[threadIdx.x * NH + n] * QSCALE;   // 128 threads == DH
    __syncthreads();
    float acc = 0.f;
#pragma unroll 8
    for (int i = 0; i < DH; i++)
        acc += qs[i] * Wk[(size_t)(i*NH + n)*MD + m];
    g_w8[m*NH + n] = acc;
}

// ------- k3: fused scores + online softmax + pooling (512 thr, 4 cols/thr) -------
__global__ __launch_bounds__(MTPB, 1) void k_main(const float* __restrict__ mem){
    extern __shared__ float sm[];
    float* rowbuf = sm;                         // 2*TR*MD          (32768 f)
    float* partf  = sm + 2*TR*MD;               // TR*256*8         (16384 f)
    float* srow2  = partf + TR*256*8;           // TR*2*8           (128 f)
    float* esm    = srow2 + TR*2*8;             // TR*NH            (64 f)
    float* scs    = esm + TR*NH;                // NH
    int*   sflag  = (int*)(scs + NH);           // 1
    const int t = threadIdx.x, b = blockIdx.x;
    const int lane = t & 31, wid = t >> 5;

    const int baseCnt = NT / GB, rem = NT % GB;
    const int cnt   = baseCnt + (b < rem ? 1 : 0);
    const int start = b * baseCnt + (b < rem ? b : rem);

    // per-thread weights for its 4 consecutive columns c = t*4+k
    float w[4][8];
#pragma unroll
    for (int k = 0; k < 4; k++){
        const float4* wp = (const float4*)(g_w8 + (t*4 + k)*8);
        float4 a = wp[0], d4 = wp[1];
        w[k][0]=a.x;  w[k][1]=a.y;  w[k][2]=a.z;  w[k][3]=a.w;
        w[k][4]=d4.x; w[k][5]=d4.y; w[k][6]=d4.z; w[k][7]=d4.w;
    }
    float p[8][4];   // [n][k] pooled accumulators (cols t*4+k)
#pragma unroll
    for (int n = 0; n < 8; n++)
#pragma unroll
        for (int k = 0; k < 4; k++) p[n][k] = 0.f;
    float mcur = -INFINITY, Zc = 0.f;   // live in warp0 lanes<8

    auto issue = [&](int tileIdx, int dbuf){
        const float* src = mem + (size_t)tileIdx * (TR*MD);
        float* dst = rowbuf + dbuf * (TR*MD);
#pragma unroll
        for (int j = 0; j < 8; j++){
            int idx = t + j*MTPB;
            cp16(dst + idx*4, src + idx*4);
        }
    };
    if (cnt > 0) issue(start, 0);
    asm volatile("cp.async.commit_group;");
    if (cnt > 1) issue(start + 1, 1);
    asm volatile("cp.async.commit_group;");

    for (int it = 0; it < cnt; it++){
        asm volatile("cp.async.wait_group 1;");
        __syncthreads();
        const float* buf = rowbuf + (it & 1) * (TR*MD);

        // Phase A: partial scores; xor-1 pre-reduce; even lanes store pair-partials
#pragma unroll
        for (int r = 0; r < TR; r++){
            float4 rv4 = *(const float4*)(buf + r*MD + t*4);
            float rv[4] = {rv4.x, rv4.y, rv4.z, rv4.w};
            float acc[8];
#pragma unroll
            for (int n = 0; n < 8; n++) acc[n] = rv[0]*w[0][n];
#pragma unroll
            for (int k = 1; k < 4; k++)
#pragma unroll
                for (int n = 0; n < 8; n++) acc[n] += rv[k]*w[k][n];
#pragma unroll
            for (int n = 0; n < 8; n++) acc[n] += __shfl_xor_sync(0xffffffffu, acc[n], 1);
            if ((lane & 1) == 0){
                float* dst = partf + (r*256 + (t >> 1))*8;
                ((float4*)dst)[0] = make_float4(acc[0], acc[1], acc[2], acc[3]);
                ((float4*)dst)[1] = make_float4(acc[4], acc[5], acc[6], acc[7]);
            }
        }
        __syncthreads();

        // Phase B: 16 warps; warp (r,half) reduces its 256 float4s
        {
            int r = wid >> 1, half = wid & 1;
            const float4* prow = (const float4*)(partf + r*2048) + half*256 + lane;
            float4 s = prow[0];
#pragma unroll
            for (int i = 1; i < 8; i++){
                float4 v = prow[32*i];
                s.x += v.x; s.y += v.y; s.z += v.z; s.w += v.w;
            }
#pragma unroll
            for (int o = 2; o <= 16; o <<= 1){
                s.x += __shfl_xor_sync(0xffffffffu, s.x, o);
                s.y += __shfl_xor_sync(0xffffffffu, s.y, o);
                s.z += __shfl_xor_sync(0xffffffffu, s.z, o);
                s.w += __shfl_xor_sync(0xffffffffu, s.w, o);
            }
            // lane0: heads 0-3 total, lane1: heads 4-7 total (parity-preserving xor)
            if (lane < 2)
                ((float4*)(srow2 + (r*2 + half)*8))[lane] = s;
        }
        __syncthreads();

        // Phase C: online-softmax bookkeeping (warp 0; lanes<8 do the work)
        if (wid == 0){
            float sc = 1.f;
            if (lane < 8){
                int n = lane;
                float sr[TR];
#pragma unroll
                for (int r = 0; r < TR; r++)
                    sr[r] = srow2[(r*2)*8 + n] + srow2[(r*2 + 1)*8 + n];
                float tm = sr[0];
#pragma unroll
                for (int r = 1; r < TR; r++) tm = fmaxf(tm, sr[r]);
                float mnew = fmaxf(mcur, tm);
                sc = __expf(mcur - mnew);   // 0 on first tile
                float zl = 0.f;
#pragma unroll
                for (int r = 0; r < TR; r++){
                    float e = __expf(sr[r] - mnew);
                    esm[r*8 + n] = e;
                    zl += e;
                }
                Zc = Zc*sc + zl;
                mcur = mnew;
                scs[n] = sc;
            }
            unsigned bal = __ballot_sync(0xffffffffu, (lane < 8) ? (sc == 1.f) : true);
            if (lane == 0) *sflag = (bal == 0xffffffffu);
        }
        __syncthreads();

        // Phase D: (conditional) rescale + weighted accumulation
        {
            if (!*sflag){
                float s8[8];
                const float4* sp = (const float4*)scs;
                float4 a = sp[0], d4 = sp[1];
                s8[0]=a.x; s8[1]=a.y; s8[2]=a.z; s8[3]=a.w;
                s8[4]=d4.x; s8[5]=d4.y; s8[6]=d4.z; s8[7]=d4.w;
#pragma unroll
                for (int n = 0; n < 8; n++)
#pragma unroll
                    for (int k = 0; k < 4; k++) p[n][k] *= s8[n];
            }
#pragma unroll
            for (int r = 0; r < TR; r++){
                float4 rv4 = *(const float4*)(buf + r*MD + t*4);
                float rv[4] = {rv4.x, rv4.y, rv4.z, rv4.w};
                const float4* ep = (const float4*)(esm + r*8);
                float4 e0 = ep[0], e1 = ep[1];
                float ev[8] = {e0.x,e0.y,e0.z,e0.w, e1.x,e1.y,e1.z,e1.w};
#pragma unroll
                for (int n = 0; n < 8; n++)
#pragma unroll
                    for (int k = 0; k < 4; k++) p[n][k] += ev[n]*rv[k];
            }
        }
        __syncthreads();
        if (it + 2 < cnt) issue(start + it + 2, it & 1);
        asm volatile("cp.async.commit_group;");
    }

    // write per-block partial (m, Z, pooled): thread owns cols t*4..t*4+3
    if (t < 8){ g_pm[b*8 + t] = mcur; g_pz[b*8 + t] = Zc; }
#pragma unroll
    for (int n = 0; n < 8; n++){
        float* dst = g_pp + (size_t)(b*8 + n)*MD;
        ((float4*)dst)[t] = make_float4(p[n][0], p[n][1], p[n][2], p[n][3]);
    }
}

// -------- k_comb (R8 version): parallel weighted reduction of partials --------
#define CTPB 128
__global__ __launch_bounds__(CTPB) void k_comb(){
    int n   = blockIdx.x >> 4;                            // 8 heads
    int col = (blockIdx.x & 15) * CTPB + threadIdx.x;     // 16 col blocks
    int lane = threadIdx.x & 31, wid = threadIdx.x >> 5;
    __shared__ float S[GB];
    __shared__ float invZsh;
    if (wid == 0){
        float m = -INFINITY;
#pragma unroll
        for (int j = 0; j < 5; j++){
            int bb = lane + 32*j;
            if (bb < GB) m = fmaxf(m, g_pm[bb*8 + n]);
        }
        m = warp_max(m);
        float z = 0.f;
#pragma unroll
        for (int j = 0; j < 5; j++){
            int bb = lane + 32*j;
            if (bb < GB){
                float s = __expf(g_pm[bb*8 + n] - m);
                S[bb] = s;
                z += g_pz[bb*8 + n] * s;
            }
        }
        z = warp_sum(z);
        if (lane == 0) invZsh = 1.f / z;
    }
    __syncthreads();
    const float* base = g_pp + (size_t)n*MD + col;
    float acc = 0.f;
#pragma unroll 8
    for (int bb = 0; bb < GB; bb++)
        acc += S[bb] * base[(size_t)bb * (8*MD)];
    g_pooled[n*MD + col] = acc * invZsh;
}

// ---- k5: feat[h] = pooled[h%8].Wv[h,:] + bv[h]  (2 warps per output) ----
__global__ __launch_bounds__(TPB) void k_feat(const float* __restrict__ Wv,
                                              const float* __restrict__ bv){
    __shared__ float sh[4][2];
    int lane = threadIdx.x & 31, wid = threadIdx.x >> 5;
    int local = wid >> 1, half = wid & 1;
    int h = blockIdx.x * 4 + local;
    int n = h & 7;
    const float4* wr = (const float4*)(Wv + (size_t)h*MD) + half*256;
    const float4* pr = (const float4*)(g_pooled + (size_t)n*MD) + half*256;
    float acc = 0.f;
#pragma unroll
    for (int i = 0; i < 8; i++){
        float4 a = wr[lane + 32*i];
        float4 v = pr[lane + 32*i];
        acc += a.x*v.x + a.y*v.y + a.z*v.z + a.w*v.w;
    }
    acc = warp_sum(acc);
    if (lane == 0) sh[local][half] = acc;
    __syncthreads();
    if (threadIdx.x < 4){
        int hh = blockIdx.x * 4 + threadIdx.x;
        g_feat[hh] = sh[threadIdx.x][0] + sh[threadIdx.x][1] + bv[hh];
    }
}

// ---- k6: out = relu([x,feat] @ Wo^T + bo)  (2 warps per output) ----
__global__ __launch_bounds__(TPB) void k_out(const float* __restrict__ x,
                                             const float* __restrict__ Wo,
                                             const float* __restrict__ bo,
                                             float* __restrict__ out){
    __shared__ float sh[4][2];
    int lane = threadIdx.x & 31, wid = threadIdx.x >> 5;
    int local = wid >> 1, half = wid & 1;
    int o = blockIdx.x * 4 + local;
    const float4* wr = (const float4*)(Wo + (size_t)o*(2*HDIM)) + half*256;
    const float4* vr = half ? (const float4*)g_feat : (const float4*)x;
    float acc = 0.f;
#pragma unroll
    for (int i = 0; i < 8; i++){
        int idx = lane + 32*i;
        float4 a = wr[idx];
        float4 v = vr[idx];
        acc += a.x*v.x + a.y*v.y + a.z*v.z + a.w*v.w;
    }
    acc = warp_sum(acc);
    if (lane == 0) sh[local][half] = acc;
    __syncthreads();
    if (threadIdx.x < 4){
        int oo = blockIdx.x * 4 + threadIdx.x;
        out[oo] = fmaxf(sh[threadIdx.x][0] + sh[threadIdx.x][1] + bo[oo], 0.f);
    }
}

extern "C" void kernel_launch(void* const* d_in, const int* in_sizes, int n_in,
                              void* d_out, int out_size){
    (void)in_sizes; (void)n_in; (void)out_size;
    const float* x   = (const float*)d_in[0];
    const float* mem = (const float*)d_in[1];
    const float* Wq  = (const float*)d_in[2];
    const float* bq  = (const float*)d_in[3];
    const float* Wk  = (const float*)d_in[4];
    // d_in[5] = bk: constant per head -> cancels in softmax, unused
    const float* Wv  = (const float*)d_in[6];
    const float* bv  = (const float*)d_in[7];
    const float* Wo  = (const float*)d_in[8];
    const float* bo  = (const float*)d_in[9];
    float* out = (float*)d_out;

    const size_t smem = (size_t)(2*TR*MD + TR*256*8 + TR*2*8 + TR*NH + NH + 1) * sizeof(float);
    cudaFuncSetAttribute(k_main, cudaFuncAttributeMaxDynamicSharedMemorySize, (int)smem);

    k_q   <<<HDIM/8,        TPB>>>(x, Wq, bq);
    k_w8  <<<(MD/WTPB)*NH,  WTPB>>>(Wk);
    k_main<<<GB,            MTPB, smem>>>(mem);
    k_comb<<<NH*16,         CTPB>>>();
    k_feat<<<HDIM/4,        TPB>>>(Wv, bv);
    k_out <<<(2*HDIM)/8,    TPB>>>(x, Wo, bo, out);
}

// round 14
// speedup vs baseline: 1.4718x; 1.1679x over previous
#include <cuda_runtime.h>
#include <math.h>
#include <stdint.h>

#define HDIM 1024
#define MD   2048
#define LMEM 16384
#define NH   8
#define DH   128
#define TPB  256
#define TR4  4              // rows per k_main tile
#define NT4  (LMEM/TR4)     // 4096 row-tiles
#define NPAIR 152           // row-range pairs (one per SM)
#define GB   152
#define QSCALE 0.08838834764831845f   // 1/sqrt(128)

// __device__ scratch (no allocations allowed)
__device__ float g_q[HDIM];
__device__ float g_w8[MD*NH];
__device__ float g_pm[NPAIR*NH];
__device__ float g_pz[NPAIR*NH];
__device__ float g_pp[NPAIR*NH*MD];
__device__ float g_pooled[NH*MD];
__device__ float g_feat[HDIM];

__device__ __forceinline__ float warp_sum(float v){
#pragma unroll
    for (int o = 16; o; o >>= 1) v += __shfl_xor_sync(0xffffffffu, v, o);
    return v;
}
__device__ __forceinline__ float warp_max(float v){
#pragma unroll
    for (int o = 16; o; o >>= 1) v = fmaxf(v, __shfl_xor_sync(0xffffffffu, v, o));
    return v;
}

__device__ __forceinline__ void cp16(float* dst, const float* src){
    uint32_t s = (uint32_t)__cvta_generic_to_shared(dst);
    asm volatile("cp.async.cg.shared.global [%0], [%1], 16;" :: "r"(s), "l"(src));
}

// ---------------- k1: q = x @ Wq^T + bq  (warp per output) ----------------
__global__ __launch_bounds__(TPB) void k_q(const float* __restrict__ x,
                                           const float* __restrict__ Wq,
                                           const float* __restrict__ bq){
    int lane = threadIdx.x & 31;
    int h = blockIdx.x * 8 + (threadIdx.x >> 5);
    const float4* xr = (const float4*)x;
    const float4* wr = (const float4*)(Wq + (size_t)h * HDIM);
    float acc = 0.f;
#pragma unroll
    for (int i = 0; i < 8; i++){
        float4 a = wr[lane + 32*i];
        float4 b = xr[lane + 32*i];
        acc += a.x*b.x + a.y*b.y + a.z*b.z + a.w*b.w;
    }
    acc = warp_sum(acc);
    if (lane == 0) g_q[h] = acc + bq[h];
}

// ---------- k2: w8[m][n] = QSCALE * sum_i q[i*8+n] * Wk[i*8+n][m] ----------
#define WTPB 128
__global__ __launch_bounds__(WTPB) void k_w8(const float* __restrict__ Wk){
    int n = blockIdx.x & 7;
    int m = (blockIdx.x >> 3) * WTPB + threadIdx.x;
    __shared__ float qs[DH];
    qs[threadIdx.x] = g_q[threadIdx.x * NH + n] * QSCALE;   // 128 threads == DH
    __syncthreads();
    float acc = 0.f;
#pragma unroll 8
    for (int i = 0; i < DH; i++)
        acc += qs[i] * Wk[(size_t)(i*NH + n)*MD + m];
    g_w8[m*NH + n] = acc;
}

// ---- k3: fused scores + softmax + pooling; head-split pairs, 2 blocks/SM ----
// block b: pair = b>>1 (row range), hg = b&1 (heads hg*4..hg*4+3)
__global__ __launch_bounds__(TPB, 2) void k_main(const float* __restrict__ mem){
    extern __shared__ float sm[];
    float*  rowbuf = sm;                          // 2*TR4*MD      (16384 f)
    float4* part4  = (float4*)(sm + 2*TR4*MD);    // TR4*256 f4    (4096 f)
    float*  srow2f = sm + 2*TR4*MD + TR4*256*4;   // TR4*2*4       (32 f)
    float*  esm    = srow2f + TR4*2*4;            // TR4*4         (16 f)
    float*  scs    = esm + TR4*4;                 // 4
    int*    sflag  = (int*)(scs + 4);             // 1
    const int t = threadIdx.x;
    const int pair = blockIdx.x >> 1, hg = blockIdx.x & 1;
    const int lane = t & 31, wid = t >> 5;

    const int baseCnt = NT4 / NPAIR, rem = NT4 % NPAIR;      // 26, 144
    const int cnt   = baseCnt + (pair < rem ? 1 : 0);
    const int start = pair * baseCnt + (pair < rem ? pair : rem);

    // per-thread weights: 8 cols x 4 heads (hg group)
    float w[8][4];
#pragma unroll
    for (int k = 0; k < 8; k++){
        int c = (k < 4) ? (t*4 + k) : (1024 + t*4 + (k - 4));
        float4 a = *(const float4*)(g_w8 + c*8 + hg*4);
        w[k][0]=a.x; w[k][1]=a.y; w[k][2]=a.z; w[k][3]=a.w;
    }
    float p[4][8];   // [head][col] pooled accumulators
#pragma unroll
    for (int nn = 0; nn < 4; nn++)
#pragma unroll
        for (int k = 0; k < 8; k++) p[nn][k] = 0.f;
    float mcur = -INFINITY, Zc = 0.f;   // live in warp0 lanes<4

    auto issue = [&](int tileIdx, int dbuf){
        const float* src = mem + (size_t)tileIdx * (TR4*MD);
        float* dst = rowbuf + dbuf * (TR4*MD);
#pragma unroll
        for (int j = 0; j < 8; j++){
            int idx = t + j*TPB;       // 2048 float4 = 32KB tile
            cp16(dst + idx*4, src + idx*4);
        }
    };
    if (cnt > 0) issue(start, 0);
    asm volatile("cp.async.commit_group;");
    if (cnt > 1) issue(start + 1, 1);
    asm volatile("cp.async.commit_group;");

    for (int it = 0; it < cnt; it++){
        asm volatile("cp.async.wait_group 1;");
        __syncthreads();
        const float* buf = rowbuf + (it & 1) * (TR4*MD);

        // Phase A: per-thread partial scores (4 heads) for TR4 rows, packed STS.128
#pragma unroll
        for (int r = 0; r < TR4; r++){
            const float4* rp = (const float4*)(buf + r*MD + t*4);
            float4 r0 = rp[0], r1 = rp[256];
            float rv[8] = {r0.x,r0.y,r0.z,r0.w, r1.x,r1.y,r1.z,r1.w};
            float acc[4];
#pragma unroll
            for (int nn = 0; nn < 4; nn++) acc[nn] = rv[0]*w[0][nn];
#pragma unroll
            for (int k = 1; k < 8; k++)
#pragma unroll
                for (int nn = 0; nn < 4; nn++) acc[nn] += rv[k]*w[k][nn];
            part4[r*TPB + t] = make_float4(acc[0], acc[1], acc[2], acc[3]);
        }
        __syncthreads();

        // Phase B: 8 warps; warp (r,half) reduces 128 float4s of row r
        {
            int r = wid >> 1, half = wid & 1;
            const float4* prow = part4 + r*TPB + half*128 + lane;
            float4 s = prow[0];
#pragma unroll
            for (int i = 1; i < 4; i++){
                float4 v = prow[32*i];
                s.x += v.x; s.y += v.y; s.z += v.z; s.w += v.w;
            }
#pragma unroll
            for (int o = 1; o <= 16; o <<= 1){
                s.x += __shfl_xor_sync(0xffffffffu, s.x, o);
                s.y += __shfl_xor_sync(0xffffffffu, s.y, o);
                s.z += __shfl_xor_sync(0xffffffffu, s.z, o);
                s.w += __shfl_xor_sync(0xffffffffu, s.w, o);
            }
            if (lane == 0) ((float4*)srow2f)[r*2 + half] = s;
        }
        __syncthreads();

        // Phase C: online-softmax bookkeeping (warp 0; lanes<4 = heads)
        if (wid == 0){
            float sc = 1.f;
            if (lane < 4){
                int nn = lane;
                float sr[TR4];
#pragma unroll
                for (int r = 0; r < TR4; r++)
                    sr[r] = srow2f[(r*2)*4 + nn] + srow2f[(r*2 + 1)*4 + nn];
                float tm = sr[0];
#pragma unroll
                for (int r = 1; r < TR4; r++) tm = fmaxf(tm, sr[r]);
                float mnew = fmaxf(mcur, tm);
                sc = __expf(mcur - mnew);   // 0 on first tile
                float zl = 0.f;
#pragma unroll
                for (int r = 0; r < TR4; r++){
                    float e = __expf(sr[r] - mnew);
                    esm[r*4 + nn] = e;
                    zl += e;
                }
                Zc = Zc*sc + zl;
                mcur = mnew;
                scs[nn] = sc;
            }
            unsigned bal = __ballot_sync(0xffffffffu, (lane < 4) ? (sc == 1.f) : true);
            if (lane == 0) *sflag = (bal == 0xffffffffu);
        }
        __syncthreads();

        // Phase D: (conditional) rescale + weighted accumulation
        {
            if (!*sflag){
                float4 s4 = *(const float4*)scs;
                float ss[4] = {s4.x, s4.y, s4.z, s4.w};
#pragma unroll
                for (int nn = 0; nn < 4; nn++)
#pragma unroll
                    for (int k = 0; k < 8; k++) p[nn][k] *= ss[nn];
            }
#pragma unroll
            for (int r = 0; r < TR4; r++){
                const float4* rp = (const float4*)(buf + r*MD + t*4);
                float4 r0 = rp[0], r1 = rp[256];
                float rv[8] = {r0.x,r0.y,r0.z,r0.w, r1.x,r1.y,r1.z,r1.w};
                float4 e4 = *(const float4*)(esm + r*4);
                float ev[4] = {e4.x, e4.y, e4.z, e4.w};
#pragma unroll
                for (int nn = 0; nn < 4; nn++)
#pragma unroll
                    for (int k = 0; k < 8; k++) p[nn][k] += ev[nn]*rv[k];
            }
        }
        __syncthreads();
        if (it + 2 < cnt) issue(start + it + 2, it & 1);
        asm volatile("cp.async.commit_group;");
    }

    // write per-block partial (m, Z, pooled) for this head group
    if (wid == 0 && lane < 4){
        g_pm[pair*8 + hg*4 + lane] = mcur;
        g_pz[pair*8 + hg*4 + lane] = Zc;
    }
#pragma unroll
    for (int nn = 0; nn < 4; nn++){
        float* dst = g_pp + (size_t)(pair*8 + hg*4 + nn)*MD;
        ((float4*)dst)[t]       = make_float4(p[nn][0], p[nn][1], p[nn][2], p[nn][3]);
        ((float4*)dst)[256 + t] = make_float4(p[nn][4], p[nn][5], p[nn][6], p[nn][7]);
    }
}

// -------- k_comb (R8 version): parallel weighted reduction of partials --------
#define CTPB 128
__global__ __launch_bounds__(CTPB) void k_comb(){
    int n   = blockIdx.x >> 4;                            // 8 heads
    int col = (blockIdx.x & 15) * CTPB + threadIdx.x;     // 16 col blocks
    int lane = threadIdx.x & 31, wid = threadIdx.x >> 5;
    __shared__ float S[GB];
    __shared__ float invZsh;
    if (wid == 0){
        float m = -INFINITY;
#pragma unroll
        for (int j = 0; j < 5; j++){
            int bb = lane + 32*j;
            if (bb < GB) m = fmaxf(m, g_pm[bb*8 + n]);
        }
        m = warp_max(m);
        float z = 0.f;
#pragma unroll
        for (int j = 0; j < 5; j++){
            int bb = lane + 32*j;
            if (bb < GB){
                float s = __expf(g_pm[bb*8 + n] - m);
                S[bb] = s;
                z += g_pz[bb*8 + n] * s;
            }
        }
        z = warp_sum(z);
        if (lane == 0) invZsh = 1.f / z;
    }
    __syncthreads();
    const float* base = g_pp + (size_t)n*MD + col;
    float acc = 0.f;
#pragma unroll 8
    for (int bb = 0; bb < GB; bb++)
        acc += S[bb] * base[(size_t)bb * (8*MD)];
    g_pooled[n*MD + col] = acc * invZsh;
}

// ---- k5: feat[h] = pooled[h%8].Wv[h,:] + bv[h]  (2 warps per output) ----
__global__ __launch_bounds__(TPB) void k_feat(const float* __restrict__ Wv,
                                              const float* __restrict__ bv){
    __shared__ float sh[4][2];
    int lane = threadIdx.x & 31, wid = threadIdx.x >> 5;
    int local = wid >> 1, half = wid & 1;
    int h = blockIdx.x * 4 + local;
    int n = h & 7;
    const float4* wr = (const float4*)(Wv + (size_t)h*MD) + half*256;
    const float4* pr = (const float4*)(g_pooled + (size_t)n*MD) + half*256;
    float acc = 0.f;
#pragma unroll
    for (int i = 0; i < 8; i++){
        float4 a = wr[lane + 32*i];
        float4 v = pr[lane + 32*i];
        acc += a.x*v.x + a.y*v.y + a.z*v.z + a.w*v.w;
    }
    acc = warp_sum(acc);
    if (lane == 0) sh[local][half] = acc;
    __syncthreads();
    if (threadIdx.x < 4){
        int hh = blockIdx.x * 4 + threadIdx.x;
        g_feat[hh] = sh[threadIdx.x][0] + sh[threadIdx.x][1] + bv[hh];
    }
}

// ---- k6: out = relu([x,feat] @ Wo^T + bo)  (2 warps per output) ----
__global__ __launch_bounds__(TPB) void k_out(const float* __restrict__ x,
                                             const float* __restrict__ Wo,
                                             const float* __restrict__ bo,
                                             float* __restrict__ out){
    __shared__ float sh[4][2];
    int lane = threadIdx.x & 31, wid = threadIdx.x >> 5;
    int local = wid >> 1, half = wid & 1;
    int o = blockIdx.x * 4 + local;
    const float4* wr = (const float4*)(Wo + (size_t)o*(2*HDIM)) + half*256;
    const float4* vr = half ? (const float4*)g_feat : (const float4*)x;
    float acc = 0.f;
#pragma unroll
    for (int i = 0; i < 8; i++){
        int idx = lane + 32*i;
        float4 a = wr[idx];
        float4 v = vr[idx];
        acc += a.x*v.x + a.y*v.y + a.z*v.z + a.w*v.w;
    }
    acc = warp_sum(acc);
    if (lane == 0) sh[local][half] = acc;
    __syncthreads();
    if (threadIdx.x < 4){
        int oo = blockIdx.x * 4 + threadIdx.x;
        out[oo] = fmaxf(sh[threadIdx.x][0] + sh[threadIdx.x][1] + bo[oo], 0.f);
    }
}

extern "C" void kernel_launch(void* const* d_in, const int* in_sizes, int n_in,
                              void* d_out, int out_size){
    (void)in_sizes; (void)n_in; (void)out_size;
    const float* x   = (const float*)d_in[0];
    const float* mem = (const float*)d_in[1];
    const float* Wq  = (const float*)d_in[2];
    const float* bq  = (const float*)d_in[3];
    const float* Wk  = (const float*)d_in[4];
    // d_in[5] = bk: constant per head -> cancels in softmax, unused
    const float* Wv  = (const float*)d_in[6];
    const float* bv  = (const float*)d_in[7];
    const float* Wo  = (const float*)d_in[8];
    const float* bo  = (const float*)d_in[9];
    float* out = (float*)d_out;

    const size_t smem = (size_t)(2*TR4*MD + TR4*256*4 + TR4*2*4 + TR4*4 + 4 + 1) * sizeof(float); // ~82KB
    cudaFuncSetAttribute(k_main, cudaFuncAttributeMaxDynamicSharedMemorySize, (int)smem);

    k_q   <<<HDIM/8,        TPB>>>(x, Wq, bq);
    k_w8  <<<(MD/WTPB)*NH,  WTPB>>>(Wk);
    k_main<<<2*NPAIR,       TPB, smem>>>(mem);
    k_comb<<<NH*16,         CTPB>>>();
    k_feat<<<HDIM/4,        TPB>>>(Wv, bv);
    k_out <<<(2*HDIM)/8,    TPB>>>(x, Wo, bo, out);
}

// round 16
// speedup vs baseline: 1.4957x; 1.0163x over previous
#include <cuda_runtime.h>
#include <math.h>
#include <stdint.h>

#define HDIM 1024
#define MD   2048
#define LMEM 16384
#define NH   8
#define DH   128
#define TPB  256
#define TR4  4              // rows per k_main tile
#define NT4  (LMEM/TR4)     // 4096 row-tiles
#define NPAIR 152           // row-range pairs (one per SM)
#define GB   152
#define QSCALE 0.08838834764831845f   // 1/sqrt(128)

// __device__ scratch (no allocations allowed)
__device__ float g_q[HDIM];
__device__ float g_w8[MD*NH];
__device__ float g_pm[NPAIR*NH];
__device__ float g_pz[NPAIR*NH];
__device__ float g_pp[NPAIR*NH*MD];
__device__ float g_pooled[NH*MD];
__device__ float g_feat[HDIM];

__device__ __forceinline__ float warp_sum(float v){
#pragma unroll
    for (int o = 16; o; o >>= 1) v += __shfl_xor_sync(0xffffffffu, v, o);
    return v;
}
__device__ __forceinline__ float warp_max(float v){
#pragma unroll
    for (int o = 16; o; o >>= 1) v = fmaxf(v, __shfl_xor_sync(0xffffffffu, v, o));
    return v;
}

__device__ __forceinline__ void cp16(float* dst, const float* src){
    uint32_t s = (uint32_t)__cvta_generic_to_shared(dst);
    asm volatile("cp.async.cg.shared.global [%0], [%1], 16;" :: "r"(s), "l"(src));
}

// ---------------- k1: q = x @ Wq^T + bq  (warp per output) ----------------
__global__ __launch_bounds__(TPB) void k_q(const float* __restrict__ x,
                                           const float* __restrict__ Wq,
                                           const float* __restrict__ bq){
    int lane = threadIdx.x & 31;
    int h = blockIdx.x * 8 + (threadIdx.x >> 5);
    const float4* xr = (const float4*)x;
    const float4* wr = (const float4*)(Wq + (size_t)h * HDIM);
    float acc = 0.f;
#pragma unroll
    for (int i = 0; i < 8; i++){
        float4 a = wr[lane + 32*i];
        float4 b = xr[lane + 32*i];
        acc += a.x*b.x + a.y*b.y + a.z*b.z + a.w*b.w;
    }
    acc = warp_sum(acc);
    if (lane == 0) g_q[h] = acc + bq[h];
}

// ---------- k2: w8[m][n] = QSCALE * sum_i q[i*8+n] * Wk[i*8+n][m] ----------
#define WTPB 128
__global__ __launch_bounds__(WTPB) void k_w8(const float* __restrict__ Wk){
    int n = blockIdx.x & 7;
    int m = (blockIdx.x >> 3) * WTPB + threadIdx.x;
    __shared__ float qs[DH];
    qs[threadIdx.x] = g_q[threadIdx.x * NH + n] * QSCALE;   // 128 threads == DH
    __syncthreads();
    float acc = 0.f;
#pragma unroll 8
    for (int i = 0; i < DH; i++)
        acc += qs[i] * Wk[(size_t)(i*NH + n)*MD + m];
    g_w8[m*NH + n] = acc;
}

// ---- k3: fused scores + softmax + pooling; head-split pairs, 2 blocks/SM ----
// block b: pair = b>>1 (row range), hg = b&1 (heads hg*4..hg*4+3)
// Row values stay in registers between Phase A and Phase D (no smem reload).
__global__ __launch_bounds__(TPB, 2) void k_main(const float* __restrict__ mem){
    extern __shared__ float sm[];
    float*  rowbuf = sm;                          // 2*TR4*MD      (16384 f)
    float4* part4  = (float4*)(sm + 2*TR4*MD);    // TR4*256 f4    (4096 f)
    float*  srow2f = sm + 2*TR4*MD + TR4*256*4;   // TR4*2*4       (32 f)
    float*  esm    = srow2f + TR4*2*4;            // TR4*4         (16 f)
    float*  scs    = esm + TR4*4;                 // 4
    int*    sflag  = (int*)(scs + 4);             // 1
    const int t = threadIdx.x;
    const int pair = blockIdx.x >> 1, hg = blockIdx.x & 1;
    const int lane = t & 31, wid = t >> 5;

    const int baseCnt = NT4 / NPAIR, rem = NT4 % NPAIR;      // 26, 144
    const int cnt   = baseCnt + (pair < rem ? 1 : 0);
    const int start = pair * baseCnt + (pair < rem ? pair : rem);

    // per-thread weights: 8 cols x 4 heads (hg group)
    float w[8][4];
#pragma unroll
    for (int k = 0; k < 8; k++){
        int c = (k < 4) ? (t*4 + k) : (1024 + t*4 + (k - 4));
        float4 a = *(const float4*)(g_w8 + c*8 + hg*4);
        w[k][0]=a.x; w[k][1]=a.y; w[k][2]=a.z; w[k][3]=a.w;
    }
    float p[4][8];   // [head][col] pooled accumulators
#pragma unroll
    for (int nn = 0; nn < 4; nn++)
#pragma unroll
        for (int k = 0; k < 8; k++) p[nn][k] = 0.f;
    float mcur = -INFINITY, Zc = 0.f;   // live in warp0 lanes<4

    auto issue = [&](int tileIdx, int dbuf){
        const float* src = mem + (size_t)tileIdx * (TR4*MD);
        float* dst = rowbuf + dbuf * (TR4*MD);
#pragma unroll
        for (int j = 0; j < 8; j++){
            int idx = t + j*TPB;       // 2048 float4 = 32KB tile
            cp16(dst + idx*4, src + idx*4);
        }
    };
    if (cnt > 0) issue(start, 0);
    asm volatile("cp.async.commit_group;");
    if (cnt > 1) issue(start + 1, 1);
    asm volatile("cp.async.commit_group;");

    for (int it = 0; it < cnt; it++){
        asm volatile("cp.async.wait_group 1;");
        __syncthreads();
        const float* buf = rowbuf + (it & 1) * (TR4*MD);

        // Phase A: load rows to REGISTERS, partial scores (4 heads), STS.128
        float rvv[TR4][8];
#pragma unroll
        for (int r = 0; r < TR4; r++){
            const float4* rp = (const float4*)(buf + r*MD + t*4);
            float4 r0 = rp[0], r1 = rp[256];
            rvv[r][0]=r0.x; rvv[r][1]=r0.y; rvv[r][2]=r0.z; rvv[r][3]=r0.w;
            rvv[r][4]=r1.x; rvv[r][5]=r1.y; rvv[r][6]=r1.z; rvv[r][7]=r1.w;
            float acc[4];
#pragma unroll
            for (int nn = 0; nn < 4; nn++) acc[nn] = rvv[r][0]*w[0][nn];
#pragma unroll
            for (int k = 1; k < 8; k++)
#pragma unroll
                for (int nn = 0; nn < 4; nn++) acc[nn] += rvv[r][k]*w[k][nn];
            part4[r*TPB + t] = make_float4(acc[0], acc[1], acc[2], acc[3]);
        }
        __syncthreads();

        // Phase B: 8 warps; warp (r,half) reduces 128 float4s of row r
        {
            int r = wid >> 1, half = wid & 1;
            const float4* prow = part4 + r*TPB + half*128 + lane;
            float4 s = prow[0];
#pragma unroll
            for (int i = 1; i < 4; i++){
                float4 v = prow[32*i];
                s.x += v.x; s.y += v.y; s.z += v.z; s.w += v.w;
            }
#pragma unroll
            for (int o = 1; o <= 16; o <<= 1){
                s.x += __shfl_xor_sync(0xffffffffu, s.x, o);
                s.y += __shfl_xor_sync(0xffffffffu, s.y, o);
                s.z += __shfl_xor_sync(0xffffffffu, s.z, o);
                s.w += __shfl_xor_sync(0xffffffffu, s.w, o);
            }
            if (lane == 0) ((float4*)srow2f)[r*2 + half] = s;
        }
        __syncthreads();

        // Phase C: online-softmax bookkeeping (warp 0; lanes<4 = heads)
        if (wid == 0){
            float sc = 1.f;
            if (lane < 4){
                int nn = lane;
                float sr[TR4];
#pragma unroll
                for (int r = 0; r < TR4; r++)
                    sr[r] = srow2f[(r*2)*4 + nn] + srow2f[(r*2 + 1)*4 + nn];
                float tm = sr[0];
#pragma unroll
                for (int r = 1; r < TR4; r++) tm = fmaxf(tm, sr[r]);
                float mnew = fmaxf(mcur, tm);
                sc = __expf(mcur - mnew);   // 0 on first tile
                float zl = 0.f;
#pragma unroll
                for (int r = 0; r < TR4; r++){
                    float e = __expf(sr[r] - mnew);
                    esm[r*4 + nn] = e;
                    zl += e;
                }
                Zc = Zc*sc + zl;
                mcur = mnew;
                scs[nn] = sc;
            }
            unsigned bal = __ballot_sync(0xffffffffu, (lane < 4) ? (sc == 1.f) : true);
            if (lane == 0) *sflag = (bal == 0xffffffffu);
        }
        __syncthreads();

        // Phase D: (conditional) rescale + weighted accumulation from REGISTERS
        {
            if (!*sflag){
                float4 s4 = *(const float4*)scs;
                float ss[4] = {s4.x, s4.y, s4.z, s4.w};
#pragma unroll
                for (int nn = 0; nn < 4; nn++)
#pragma unroll
                    for (int k = 0; k < 8; k++) p[nn][k] *= ss[nn];
            }
#pragma unroll
            for (int r = 0; r < TR4; r++){
                float4 e4 = *(const float4*)(esm + r*4);
                float ev[4] = {e4.x, e4.y, e4.z, e4.w};
#pragma unroll
                for (int nn = 0; nn < 4; nn++)
#pragma unroll
                    for (int k = 0; k < 8; k++) p[nn][k] += ev[nn]*rvv[r][k];
            }
        }
        __syncthreads();
        if (it + 2 < cnt) issue(start + it + 2, it & 1);
        asm volatile("cp.async.commit_group;");
    }

    // write per-block partial (m, Z, pooled) for this head group
    if (wid == 0 && lane < 4){
        g_pm[pair*8 + hg*4 + lane] = mcur;
        g_pz[pair*8 + hg*4 + lane] = Zc;
    }
#pragma unroll
    for (int nn = 0; nn < 4; nn++){
        float* dst = g_pp + (size_t)(pair*8 + hg*4 + nn)*MD;
        ((float4*)dst)[t]       = make_float4(p[nn][0], p[nn][1], p[nn][2], p[nn][3]);
        ((float4*)dst)[256 + t] = make_float4(p[nn][4], p[nn][5], p[nn][6], p[nn][7]);
    }
}

// -------- k_comb (R8 version): parallel weighted reduction of partials --------
#define CTPB 128
__global__ __launch_bounds__(CTPB) void k_comb(){
    int n   = blockIdx.x >> 4;                            // 8 heads
    int col = (blockIdx.x & 15) * CTPB + threadIdx.x;     // 16 col blocks
    int lane = threadIdx.x & 31, wid = threadIdx.x >> 5;
    __shared__ float S[GB];
    __shared__ float invZsh;
    if (wid == 0){
        float m = -INFINITY;
#pragma unroll
        for (int j = 0; j < 5; j++){
            int bb = lane + 32*j;
            if (bb < GB) m = fmaxf(m, g_pm[bb*8 + n]);
        }
        m = warp_max(m);
        float z = 0.f;
#pragma unroll
        for (int j = 0; j < 5; j++){
            int bb = lane + 32*j;
            if (bb < GB){
                float s = __expf(g_pm[bb*8 + n] - m);
                S[bb] = s;
                z += g_pz[bb*8 + n] * s;
            }
        }
        z = warp_sum(z);
        if (lane == 0) invZsh = 1.f / z;
    }
    __syncthreads();
    const float* base = g_pp + (size_t)n*MD + col;
    float acc = 0.f;
#pragma unroll 8
    for (int bb = 0; bb < GB; bb++)
        acc += S[bb] * base[(size_t)bb * (8*MD)];
    g_pooled[n*MD + col] = acc * invZsh;
}

// ---- k5: feat[h] = pooled[h%8].Wv[h,:] + bv[h]  (2 warps per output) ----
__global__ __launch_bounds__(TPB) void k_feat(const float* __restrict__ Wv,
                                              const float* __restrict__ bv){
    __shared__ float sh[4][2];
    int lane = threadIdx.x & 31, wid = threadIdx.x >> 5;
    int local = wid >> 1, half = wid & 1;
    int h = blockIdx.x * 4 + local;
    int n = h & 7;
    const float4* wr = (const float4*)(Wv + (size_t)h*MD) + half*256;
    const float4* pr = (const float4*)(g_pooled + (size_t)n*MD) + half*256;
    float acc = 0.f;
#pragma unroll
    for (int i = 0; i < 8; i++){
        float4 a = wr[lane + 32*i];
        float4 v = pr[lane + 32*i];
        acc += a.x*v.x + a.y*v.y + a.z*v.z + a.w*v.w;
    }
    acc = warp_sum(acc);
    if (lane == 0) sh[local][half] = acc;
    __syncthreads();
    if (threadIdx.x < 4){
        int hh = blockIdx.x * 4 + threadIdx.x;
        g_feat[hh] = sh[threadIdx.x][0] + sh[threadIdx.x][1] + bv[hh];
    }
}

// ---- k6: out = relu([x,feat] @ Wo^T + bo)  (2 warps per output) ----
__global__ __launch_bounds__(TPB) void k_out(const float* __restrict__ x,
                                             const float* __restrict__ Wo,
                                             const float* __restrict__ bo,
                                             float* __restrict__ out){
    __shared__ float sh[4][2];
    int lane = threadIdx.x & 31, wid = threadIdx.x >> 5;
    int local = wid >> 1, half = wid & 1;
    int o = blockIdx.x * 4 + local;
    const float4* wr = (const float4*)(Wo + (size_t)o*(2*HDIM)) + half*256;
    const float4* vr = half ? (const float4*)g_feat : (const float4*)x;
    float acc = 0.f;
#pragma unroll
    for (int i = 0; i < 8; i++){
        int idx = lane + 32*i;
        float4 a = wr[idx];
        float4 v = vr[idx];
        acc += a.x*v.x + a.y*v.y + a.z*v.z + a.w*v.w;
    }
    acc = warp_sum(acc);
    if (lane == 0) sh[local][half] = acc;
    __syncthreads();
    if (threadIdx.x < 4){
        int oo = blockIdx.x * 4 + threadIdx.x;
        out[oo] = fmaxf(sh[threadIdx.x][0] + sh[threadIdx.x][1] + bo[oo], 0.f);
    }
}

extern "C" void kernel_launch(void* const* d_in, const int* in_sizes, int n_in,
                              void* d_out, int out_size){
    (void)in_sizes; (void)n_in; (void)out_size;
    const float* x   = (const float*)d_in[0];
    const float* mem = (const float*)d_in[1];
    const float* Wq  = (const float*)d_in[2];
    const float* bq  = (const float*)d_in[3];
    const float* Wk  = (const float*)d_in[4];
    // d_in[5] = bk: constant per head -> cancels in softmax, unused
    const float* Wv  = (const float*)d_in[6];
    const float* bv  = (const float*)d_in[7];
    const float* Wo  = (const float*)d_in[8];
    const float* bo  = (const float*)d_in[9];
    float* out = (float*)d_out;

    const size_t smem = (size_t)(2*TR4*MD + TR4*256*4 + TR4*2*4 + TR4*4 + 4 + 1) * sizeof(float); // ~82KB
    cudaFuncSetAttribute(k_main, cudaFuncAttributeMaxDynamicSharedMemorySize, (int)smem);

    k_q   <<<HDIM/8,        TPB>>>(x, Wq, bq);
    k_w8  <<<(MD/WTPB)*NH,  WTPB>>>(Wk);
    k_main<<<2*NPAIR,       TPB, smem>>>(mem);
    k_comb<<<NH*16,         CTPB>>>();
    k_feat<<<HDIM/4,        TPB>>>(Wv, bv);
    k_out <<<(2*HDIM)/8,    TPB>>>(x, Wo, bo, out);
}

// round 17
// speedup vs baseline: 1.5743x; 1.0525x over previous
#include <cuda_runtime.h>
#include <math.h>
#include <stdint.h>

#define HDIM 1024
#define MD   2048
#define LMEM 16384
#define NH   8
#define DH   128
#define TPB  256
#define TR4  4              // rows per k_main tile
#define NT4  (LMEM/TR4)     // 4096 row-tiles
#define NPAIR 152           // row-range pairs (one per SM)
#define GB   152
#define QSCALE 0.08838834764831845f   // 1/sqrt(128)

// __device__ scratch (no allocations allowed)
__device__ float g_q[HDIM];
__device__ float g_w8[MD*NH];
__device__ float g_pm[NPAIR*NH];
__device__ float g_pz[NPAIR*NH];
__device__ float g_pp[NPAIR*NH*MD];
__device__ float g_pooled[NH*MD];
__device__ float g_feat[HDIM];

__device__ __forceinline__ float warp_sum(float v){
#pragma unroll
    for (int o = 16; o; o >>= 1) v += __shfl_xor_sync(0xffffffffu, v, o);
    return v;
}
__device__ __forceinline__ float warp_max(float v){
#pragma unroll
    for (int o = 16; o; o >>= 1) v = fmaxf(v, __shfl_xor_sync(0xffffffffu, v, o));
    return v;
}

__device__ __forceinline__ void cp16(float* dst, const float* src){
    uint32_t s = (uint32_t)__cvta_generic_to_shared(dst);
    asm volatile("cp.async.cg.shared.global [%0], [%1], 16;" :: "r"(s), "l"(src));
}

// ---------------- k1: q = x @ Wq^T + bq  (warp per output) ----------------
__global__ __launch_bounds__(TPB) void k_q(const float* __restrict__ x,
                                           const float* __restrict__ Wq,
                                           const float* __restrict__ bq){
    int lane = threadIdx.x & 31;
    int h = blockIdx.x * 8 + (threadIdx.x >> 5);
    const float4* xr = (const float4*)x;
    const float4* wr = (const float4*)(Wq + (size_t)h * HDIM);
    float acc = 0.f;
#pragma unroll
    for (int i = 0; i < 8; i++){
        float4 a = wr[lane + 32*i];
        float4 b = xr[lane + 32*i];
        acc += a.x*b.x + a.y*b.y + a.z*b.z + a.w*b.w;
    }
    acc = warp_sum(acc);
    if (lane == 0) g_q[h] = acc + bq[h];
}

// ---------- k2: w8[m][n] = QSCALE * sum_i q[i*8+n] * Wk[i*8+n][m] ----------
#define WTPB 128
__global__ __launch_bounds__(WTPB) void k_w8(const float* __restrict__ Wk){
    int n = blockIdx.x & 7;
    int m = (blockIdx.x >> 3) * WTPB + threadIdx.x;
    __shared__ float qs[DH];
    qs[threadIdx.x] = g_q[threadIdx.x * NH + n] * QSCALE;   // 128 threads == DH
    __syncthreads();
    float acc = 0.f;
#pragma unroll 8
    for (int i = 0; i < DH; i++)
        acc += qs[i] * Wk[(size_t)(i*NH + n)*MD + m];
    g_w8[m*NH + n] = acc;
}

// ---- k3: fused scores + softmax + pooling; head-split pairs, 2 blocks/SM ----
// block b: pair = b>>1 (row range), hg = b&1 (heads hg*4..hg*4+3)
// Row values stay in registers across phases; next-tile cp.async issued right
// after Phase A (rowbuf dead from there) so DRAM fetch overlaps B+C+D.
__global__ __launch_bounds__(TPB, 2) void k_main(const float* __restrict__ mem){
    extern __shared__ float sm[];
    float*  rowbuf = sm;                          // 2*TR4*MD      (16384 f)
    float4* part4  = (float4*)(sm + 2*TR4*MD);    // TR4*256 f4    (4096 f)
    float*  srow2f = sm + 2*TR4*MD + TR4*256*4;   // TR4*2*4       (32 f)
    float*  esm    = srow2f + TR4*2*4;            // TR4*4         (16 f)
    float*  scs    = esm + TR4*4;                 // 4
    int*    sflag  = (int*)(scs + 4);             // 1
    const int t = threadIdx.x;
    const int pair = blockIdx.x >> 1, hg = blockIdx.x & 1;
    const int lane = t & 31, wid = t >> 5;

    const int baseCnt = NT4 / NPAIR, rem = NT4 % NPAIR;      // 26, 144
    const int cnt   = baseCnt + (pair < rem ? 1 : 0);
    const int start = pair * baseCnt + (pair < rem ? pair : rem);

    // per-thread weights: 8 cols x 4 heads (hg group)
    float w[8][4];
#pragma unroll
    for (int k = 0; k < 8; k++){
        int c = (k < 4) ? (t*4 + k) : (1024 + t*4 + (k - 4));
        float4 a = *(const float4*)(g_w8 + c*8 + hg*4);
        w[k][0]=a.x; w[k][1]=a.y; w[k][2]=a.z; w[k][3]=a.w;
    }
    float p[4][8];   // [head][col] pooled accumulators
#pragma unroll
    for (int nn = 0; nn < 4; nn++)
#pragma unroll
        for (int k = 0; k < 8; k++) p[nn][k] = 0.f;
    float mcur = -INFINITY, Zc = 0.f;   // live in warp0 lanes<4

    auto issue = [&](int tileIdx, int dbuf){
        const float* src = mem + (size_t)tileIdx * (TR4*MD);
        float* dst = rowbuf + dbuf * (TR4*MD);
#pragma unroll
        for (int j = 0; j < 8; j++){
            int idx = t + j*TPB;       // 2048 float4 = 32KB tile
            cp16(dst + idx*4, src + idx*4);
        }
    };
    if (cnt > 0) issue(start, 0);
    asm volatile("cp.async.commit_group;");
    if (cnt > 1) issue(start + 1, 1);
    asm volatile("cp.async.commit_group;");

    for (int it = 0; it < cnt; it++){
        asm volatile("cp.async.wait_group 1;");
        __syncthreads();
        const float* buf = rowbuf + (it & 1) * (TR4*MD);

        // Phase A: load rows to REGISTERS, partial scores (4 heads), STS.128
        float rvv[TR4][8];
#pragma unroll
        for (int r = 0; r < TR4; r++){
            const float4* rp = (const float4*)(buf + r*MD + t*4);
            float4 r0 = rp[0], r1 = rp[256];
            rvv[r][0]=r0.x; rvv[r][1]=r0.y; rvv[r][2]=r0.z; rvv[r][3]=r0.w;
            rvv[r][4]=r1.x; rvv[r][5]=r1.y; rvv[r][6]=r1.z; rvv[r][7]=r1.w;
            float acc[4];
#pragma unroll
            for (int nn = 0; nn < 4; nn++) acc[nn] = rvv[r][0]*w[0][nn];
#pragma unroll
            for (int k = 1; k < 8; k++)
#pragma unroll
                for (int nn = 0; nn < 4; nn++) acc[nn] += rvv[r][k]*w[k][nn];
            part4[r*TPB + t] = make_float4(acc[0], acc[1], acc[2], acc[3]);
        }
        __syncthreads();

        // Prefetch tile it+2 NOW: rowbuf[it&1] is dead (rows live in rvv regs),
        // and part4/srow/esm are untouched by cp.async. DRAM overlaps B+C+D.
        if (it + 2 < cnt) issue(start + it + 2, it & 1);
        asm volatile("cp.async.commit_group;");

        // Phase B: 8 warps; warp (r,half) reduces 128 float4s of row r
        {
            int r = wid >> 1, half = wid & 1;
            const float4* prow = part4 + r*TPB + half*128 + lane;
            float4 s = prow[0];
#pragma unroll
            for (int i = 1; i < 4; i++){
                float4 v = prow[32*i];
                s.x += v.x; s.y += v.y; s.z += v.z; s.w += v.w;
            }
#pragma unroll
            for (int o = 1; o <= 16; o <<= 1){
                s.x += __shfl_xor_sync(0xffffffffu, s.x, o);
                s.y += __shfl_xor_sync(0xffffffffu, s.y, o);
                s.z += __shfl_xor_sync(0xffffffffu, s.z, o);
                s.w += __shfl_xor_sync(0xffffffffu, s.w, o);
            }
            if (lane == 0) ((float4*)srow2f)[r*2 + half] = s;
        }
        __syncthreads();

        // Phase C: online-softmax bookkeeping (warp 0; lanes<4 = heads)
        if (wid == 0){
            float sc = 1.f;
            if (lane < 4){
                int nn = lane;
                float sr[TR4];
#pragma unroll
                for (int r = 0; r < TR4; r++)
                    sr[r] = srow2f[(r*2)*4 + nn] + srow2f[(r*2 + 1)*4 + nn];
                float tm = sr[0];
#pragma unroll
                for (int r = 1; r < TR4; r++) tm = fmaxf(tm, sr[r]);
                float mnew = fmaxf(mcur, tm);
                sc = __expf(mcur - mnew);   // 0 on first tile
                float zl = 0.f;
#pragma unroll
                for (int r = 0; r < TR4; r++){
                    float e = __expf(sr[r] - mnew);
                    esm[r*4 + nn] = e;
                    zl += e;
                }
                Zc = Zc*sc + zl;
                mcur = mnew;
                scs[nn] = sc;
            }
            unsigned bal = __ballot_sync(0xffffffffu, (lane < 4) ? (sc == 1.f) : true);
            if (lane == 0) *sflag = (bal == 0xffffffffu);
        }
        __syncthreads();

        // Phase D: (conditional) rescale + weighted accumulation from REGISTERS.
        // No trailing barrier: nothing after D touches shared state this
        // iteration; next iteration's wait_group+bar provides ordering.
        {
            if (!*sflag){
                float4 s4 = *(const float4*)scs;
                float ss[4] = {s4.x, s4.y, s4.z, s4.w};
#pragma unroll
                for (int nn = 0; nn < 4; nn++)
#pragma unroll
                    for (int k = 0; k < 8; k++) p[nn][k] *= ss[nn];
            }
#pragma unroll
            for (int r = 0; r < TR4; r++){
                float4 e4 = *(const float4*)(esm + r*4);
                float ev[4] = {e4.x, e4.y, e4.z, e4.w};
#pragma unroll
                for (int nn = 0; nn < 4; nn++)
#pragma unroll
                    for (int k = 0; k < 8; k++) p[nn][k] += ev[nn]*rvv[r][k];
            }
        }
    }

    // write per-block partial (m, Z, pooled) for this head group
    if (wid == 0 && lane < 4){
        g_pm[pair*8 + hg*4 + lane] = mcur;
        g_pz[pair*8 + hg*4 + lane] = Zc;
    }
#pragma unroll
    for (int nn = 0; nn < 4; nn++){
        float* dst = g_pp + (size_t)(pair*8 + hg*4 + nn)*MD;
        ((float4*)dst)[t]       = make_float4(p[nn][0], p[nn][1], p[nn][2], p[nn][3]);
        ((float4*)dst)[256 + t] = make_float4(p[nn][4], p[nn][5], p[nn][6], p[nn][7]);
    }
}

// -------- k_comb (R8 version): parallel weighted reduction of partials --------
#define CTPB 128
__global__ __launch_bounds__(CTPB) void k_comb(){
    int n   = blockIdx.x >> 4;                            // 8 heads
    int col = (blockIdx.x & 15) * CTPB + threadIdx.x;     // 16 col blocks
    int lane = threadIdx.x & 31, wid = threadIdx.x >> 5;
    __shared__ float S[GB];
    __shared__ float invZsh;
    if (wid == 0){
        float m = -INFINITY;
#pragma unroll
        for (int j = 0; j < 5; j++){
            int bb = lane + 32*j;
            if (bb < GB) m = fmaxf(m, g_pm[bb*8 + n]);
        }
        m = warp_max(m);
        float z = 0.f;
#pragma unroll
        for (int j = 0; j < 5; j++){
            int bb = lane + 32*j;
            if (bb < GB){
                float s = __expf(g_pm[bb*8 + n] - m);
                S[bb] = s;
                z += g_pz[bb*8 + n] * s;
            }
        }
        z = warp_sum(z);
        if (lane == 0) invZsh = 1.f / z;
    }
    __syncthreads();
    const float* base = g_pp + (size_t)n*MD + col;
    float acc = 0.f;
#pragma unroll 8
    for (int bb = 0; bb < GB; bb++)
        acc += S[bb] * base[(size_t)bb * (8*MD)];
    g_pooled[n*MD + col] = acc * invZsh;
}

// ---- k5: feat[h] = pooled[h%8].Wv[h,:] + bv[h]  (2 warps per output) ----
__global__ __launch_bounds__(TPB) void k_feat(const float* __restrict__ Wv,
                                              const float* __restrict__ bv){
    __shared__ float sh[4][2];
    int lane = threadIdx.x & 31, wid = threadIdx.x >> 5;
    int local = wid >> 1, half = wid & 1;
    int h = blockIdx.x * 4 + local;
    int n = h & 7;
    const float4* wr = (const float4*)(Wv + (size_t)h*MD) + half*256;
    const float4* pr = (const float4*)(g_pooled + (size_t)n*MD) + half*256;
    float acc = 0.f;
#pragma unroll
    for (int i = 0; i < 8; i++){
        float4 a = wr[lane + 32*i];
        float4 v = pr[lane + 32*i];
        acc += a.x*v.x + a.y*v.y + a.z*v.z + a.w*v.w;
    }
    acc = warp_sum(acc);
    if (lane == 0) sh[local][half] = acc;
    __syncthreads();
    if (threadIdx.x < 4){
        int hh = blockIdx.x * 4 + threadIdx.x;
        g_feat[hh] = sh[threadIdx.x][0] + sh[threadIdx.x][1] + bv[hh];
    }
}

// ---- k6: out = relu([x,feat] @ Wo^T + bo)  (2 warps per output) ----
__global__ __launch_bounds__(TPB) void k_out(const float* __restrict__ x,
                                             const float* __restrict__ Wo,
                                             const float* __restrict__ bo,
                                             float* __restrict__ out){
    __shared__ float sh[4][2];
    int lane = threadIdx.x & 31, wid = threadIdx.x >> 5;
    int local = wid >> 1, half = wid & 1;
    int o = blockIdx.x * 4 + local;
    const float4* wr = (const float4*)(Wo + (size_t)o*(2*HDIM)) + half*256;
    const float4* vr = half ? (const float4*)g_feat : (const float4*)x;
    float acc = 0.f;
#pragma unroll
    for (int i = 0; i < 8; i++){
        int idx = lane + 32*i;
        float4 a = wr[idx];
        float4 v = vr[idx];
        acc += a.x*v.x + a.y*v.y + a.z*v.z + a.w*v.w;
    }
    acc = warp_sum(acc);
    if (lane == 0) sh[local][half] = acc;
    __syncthreads();
    if (threadIdx.x < 4){
        int oo = blockIdx.x * 4 + threadIdx.x;
        out[oo] = fmaxf(sh[threadIdx.x][0] + sh[threadIdx.x][1] + bo[oo], 0.f);
    }
}

extern "C" void kernel_launch(void* const* d_in, const int* in_sizes, int n_in,
                              void* d_out, int out_size){
    (void)in_sizes; (void)n_in; (void)out_size;
    const float* x   = (const float*)d_in[0];
    const float* mem = (const float*)d_in[1];
    const float* Wq  = (const float*)d_in[2];
    const float* bq  = (const float*)d_in[3];
    const float* Wk  = (const float*)d_in[4];
    // d_in[5] = bk: constant per head -> cancels in softmax, unused
    const float* Wv  = (const float*)d_in[6];
    const float* bv  = (const float*)d_in[7];
    const float* Wo  = (const float*)d_in[8];
    const float* bo  = (const float*)d_in[9];
    float* out = (float*)d_out;

    const size_t smem = (size_t)(2*TR4*MD + TR4*256*4 + TR4*2*4 + TR4*4 + 4 + 1) * sizeof(float); // ~82KB
    cudaFuncSetAttribute(k_main, cudaFuncAttributeMaxDynamicSharedMemorySize, (int)smem);

    k_q   <<<HDIM/8,        TPB>>>(x, Wq, bq);
    k_w8  <<<(MD/WTPB)*NH,  WTPB>>>(Wk);
    k_main<<<2*NPAIR,       TPB, smem>>>(mem);
    k_comb<<<NH*16,         CTPB>>>();
    k_feat<<<HDIM/4,        TPB>>>(Wv, bv);
    k_out <<<(2*HDIM)/8,    TPB>>>(x, Wo, bo, out);
}